// round 1
// baseline (speedup 1.0000x reference)
#include <cuda_runtime.h>

#define NN 100000
#define NE 1600000
#define FIN 128
#define HID 64
#define SCAN_NBLK 98   // ceil(NN/1024)

// ---------------- scratch (device globals; no allocation allowed) ----------------
__device__ __align__(256) float g_h0[(size_t)NN * HID];   // ping
__device__ __align__(256) float g_h1[(size_t)NN * HID];   // pong
__device__ __align__(256) float g_y [(size_t)NN * 16];    // per-node edge-head partials
__device__ __align__(256) float g_dinv[NN];
__device__ __align__(256) int   g_deg[NN];
__device__ __align__(256) int   g_cursor[NN];
__device__ __align__(256) int   g_rowptr[NN + 1];
__device__ __align__(256) int   g_src[NE];
__device__ __align__(256) int   g_bsums[128];

// ---------------- CSR build ----------------
__global__ void k_zero() {
    int i = blockIdx.x * 256 + threadIdx.x;
    if (i < NN) { g_deg[i] = 0; g_cursor[i] = 0; }
}

__global__ void k_hist(const int* __restrict__ col) {
    int e = blockIdx.x * 256 + threadIdx.x;
    if (e < NE) atomicAdd(&g_deg[col[e]], 1);
}

__global__ void k_dinv() {
    int i = blockIdx.x * 256 + threadIdx.x;
    if (i < NN) g_dinv[i] = rsqrtf((float)g_deg[i] + 1.0f);  // +1 self-loop
}

__global__ __launch_bounds__(1024) void k_scan1() {
    int tid = threadIdx.x;
    int i = blockIdx.x * 1024 + tid;
    int v = (i < NN) ? g_deg[i] : 0;
    int lane = tid & 31, wid = tid >> 5;
    int x = v;
    #pragma unroll
    for (int d = 1; d < 32; d <<= 1) {
        int y = __shfl_up_sync(0xffffffffu, x, d);
        if (lane >= d) x += y;
    }
    __shared__ int wsum[32];
    if (lane == 31) wsum[wid] = x;
    __syncthreads();
    if (wid == 0) {
        int s = wsum[lane];
        int sx = s;
        #pragma unroll
        for (int d = 1; d < 32; d <<= 1) {
            int y = __shfl_up_sync(0xffffffffu, sx, d);
            if (lane >= d) sx += y;
        }
        wsum[lane] = sx - s;  // exclusive warp offsets
    }
    __syncthreads();
    int incl = x + wsum[wid];
    if (i < NN) g_rowptr[i] = incl - v;           // exclusive scan
    if (tid == 1023) g_bsums[blockIdx.x] = incl;  // block total
}

__global__ void k_scan2() {
    int t = threadIdx.x;  // 128 threads
    int v = (t < SCAN_NBLK) ? g_bsums[t] : 0;
    int lane = t & 31, wid = t >> 5;
    int x = v;
    #pragma unroll
    for (int d = 1; d < 32; d <<= 1) {
        int y = __shfl_up_sync(0xffffffffu, x, d);
        if (lane >= d) x += y;
    }
    __shared__ int ws[4];
    if (lane == 31) ws[wid] = x;
    __syncthreads();
    int off = 0;
    for (int w = 0; w < wid; w++) off += ws[w];
    int incl = x + off;
    if (t < SCAN_NBLK) g_bsums[t] = incl - v;
    if (t == SCAN_NBLK - 1) g_rowptr[NN] = incl;  // == NE
}

__global__ __launch_bounds__(1024) void k_scan3() {
    int i = blockIdx.x * 1024 + threadIdx.x;
    if (i < NN) g_rowptr[i] += g_bsums[blockIdx.x];
}

__global__ void k_fill(const int* __restrict__ row, const int* __restrict__ col) {
    int e = blockIdx.x * 256 + threadIdx.x;
    if (e < NE) {
        int c = col[e];
        int p = g_rowptr[c] + atomicAdd(&g_cursor[c], 1);
        g_src[p] = row[e];
    }
}

// ---------------- dense GEMM: C(g_h0)[n,HID] = A[n,K] @ W[K,HID] ----------------
template <int K, bool A_FROM_H1>
__global__ __launch_bounds__(256) void k_gemm(const float* __restrict__ Ain,
                                              const float* __restrict__ W) {
    __shared__ float Ws[K * HID];
    {
        const float4* W4 = reinterpret_cast<const float4*>(W);
        float4* S4 = reinterpret_cast<float4*>(Ws);
        for (int i = threadIdx.x; i < K * HID / 4; i += 256) S4[i] = W4[i];
    }
    __syncthreads();
    int rowi = blockIdx.x * 256 + threadIdx.x;
    if (rowi >= NN) return;
    const float* A = A_FROM_H1 ? g_h1 : Ain;

    float acc[HID];
    #pragma unroll
    for (int j = 0; j < HID; j++) acc[j] = 0.f;

    const float4* a4 = reinterpret_cast<const float4*>(A + (size_t)rowi * K);
    const float4* S4 = reinterpret_cast<const float4*>(Ws);
    #pragma unroll 2
    for (int k4 = 0; k4 < K / 4; k4++) {
        float4 xq = a4[k4];
        float xs[4] = {xq.x, xq.y, xq.z, xq.w};
        #pragma unroll
        for (int u = 0; u < 4; u++) {
            float xv = xs[u];
            const float4* wrow = S4 + (size_t)(k4 * 4 + u) * (HID / 4);
            #pragma unroll
            for (int j4 = 0; j4 < HID / 4; j4++) {
                float4 w = wrow[j4];
                acc[j4 * 4 + 0] += xv * w.x;
                acc[j4 * 4 + 1] += xv * w.y;
                acc[j4 * 4 + 2] += xv * w.z;
                acc[j4 * 4 + 3] += xv * w.w;
            }
        }
    }
    float4* c4 = reinterpret_cast<float4*>(g_h0 + (size_t)rowi * HID);
    #pragma unroll
    for (int j4 = 0; j4 < HID / 4; j4++)
        c4[j4] = make_float4(acc[j4 * 4], acc[j4 * 4 + 1], acc[j4 * 4 + 2], acc[j4 * 4 + 3]);
}

// ---------------- GCN aggregate: g_h1 = relu(D^-1/2 (A+I) D^-1/2 g_h0 + b) ----------------
// One warp per node; lane owns 2 features (float2).
__global__ __launch_bounds__(256) void k_agg(const float* __restrict__ bias) {
    int gw = (blockIdx.x * 256 + threadIdx.x) >> 5;
    if (gw >= NN) return;
    int lane = threadIdx.x & 31;
    float di = g_dinv[gw];
    int beg = g_rowptr[gw], end = g_rowptr[gw + 1];

    const float2* hin2 = reinterpret_cast<const float2*>(g_h0);
    float2 hself = hin2[(size_t)gw * 32 + lane];
    float sw = di * di;
    float ax = sw * hself.x, ay = sw * hself.y;

    int e = beg;
    for (; e + 2 <= end; e += 2) {
        int s0 = __ldg(&g_src[e]);
        int s1 = __ldg(&g_src[e + 1]);
        float w0 = di * __ldg(&g_dinv[s0]);
        float w1 = di * __ldg(&g_dinv[s1]);
        float2 v0 = hin2[(size_t)s0 * 32 + lane];
        float2 v1 = hin2[(size_t)s1 * 32 + lane];
        ax += w0 * v0.x + w1 * v1.x;
        ay += w0 * v0.y + w1 * v1.y;
    }
    if (e < end) {
        int s = __ldg(&g_src[e]);
        float w = di * __ldg(&g_dinv[s]);
        float2 v = hin2[(size_t)s * 32 + lane];
        ax += w * v.x;
        ay += w * v.y;
    }
    float2 b = reinterpret_cast<const float2*>(bias)[lane];
    float2 r;
    r.x = fmaxf(ax + b.x, 0.f);
    r.y = fmaxf(ay + b.y, 0.f);
    reinterpret_cast<float2*>(g_h1)[(size_t)gw * 32 + lane] = r;
}

// ---------------- edge head, node phase: g_y[i] = [h1[i]@Wl_top + bl , h1[i]@Wl_bot] ----------------
__global__ __launch_bounds__(256) void k_head(const float* __restrict__ Wl,
                                              const float* __restrict__ bl) {
    __shared__ float Ws[128 * 8];
    {
        const float4* W4 = reinterpret_cast<const float4*>(Wl);
        float4* S4 = reinterpret_cast<float4*>(Ws);
        for (int i = threadIdx.x; i < 128 * 8 / 4; i += 256) S4[i] = W4[i];
    }
    __syncthreads();
    int rowi = blockIdx.x * 256 + threadIdx.x;
    if (rowi >= NN) return;

    float acc[16];
    #pragma unroll
    for (int j = 0; j < 16; j++) acc[j] = 0.f;

    const float4* h4 = reinterpret_cast<const float4*>(g_h1 + (size_t)rowi * HID);
    const float4* S4 = reinterpret_cast<const float4*>(Ws);
    #pragma unroll 2
    for (int k4 = 0; k4 < HID / 4; k4++) {
        float4 hq = h4[k4];
        float hs[4] = {hq.x, hq.y, hq.z, hq.w};
        #pragma unroll
        for (int u = 0; u < 4; u++) {
            int k = k4 * 4 + u;
            float hv = hs[u];
            float4 t0 = S4[k * 2 + 0];
            float4 t1 = S4[k * 2 + 1];
            float4 q0 = S4[(64 + k) * 2 + 0];
            float4 q1 = S4[(64 + k) * 2 + 1];
            acc[0] += hv * t0.x;  acc[1] += hv * t0.y;  acc[2]  += hv * t0.z;  acc[3]  += hv * t0.w;
            acc[4] += hv * t1.x;  acc[5] += hv * t1.y;  acc[6]  += hv * t1.z;  acc[7]  += hv * t1.w;
            acc[8] += hv * q0.x;  acc[9] += hv * q0.y;  acc[10] += hv * q0.z;  acc[11] += hv * q0.w;
            acc[12]+= hv * q1.x;  acc[13]+= hv * q1.y;  acc[14] += hv * q1.z;  acc[15] += hv * q1.w;
        }
    }
    #pragma unroll
    for (int o = 0; o < 8; o++) acc[o] += __ldg(&bl[o]);

    float4* y4 = reinterpret_cast<float4*>(g_y + (size_t)rowi * 16);
    #pragma unroll
    for (int j4 = 0; j4 < 4; j4++)
        y4[j4] = make_float4(acc[j4 * 4], acc[j4 * 4 + 1], acc[j4 * 4 + 2], acc[j4 * 4 + 3]);
}

// ---------------- edge head, edge phase: out[e] = y[row][0:8] + y[col][8:16] ----------------
__global__ void k_edge(const int* __restrict__ row, const int* __restrict__ col,
                       float* __restrict__ out) {
    int idx = blockIdx.x * 256 + threadIdx.x;
    if (idx >= NE * 2) return;
    int e = idx >> 1, c = idx & 1;
    int r = row[e], cl = col[e];
    const float4* y4 = reinterpret_cast<const float4*>(g_y);
    float4 a = y4[(size_t)r * 4 + c];
    float4 b = y4[(size_t)cl * 4 + 2 + c];
    float4 o;
    o.x = a.x + b.x; o.y = a.y + b.y; o.z = a.z + b.z; o.w = a.w + b.w;
    reinterpret_cast<float4*>(out)[idx] = o;
}

// ---------------- launch ----------------
extern "C" void kernel_launch(void* const* d_in, const int* in_sizes, int n_in,
                              void* d_out, int out_size) {
    const float* x  = (const float*)d_in[0];
    const int*   ei = (const int*)  d_in[1];
    const float* W1 = (const float*)d_in[2];
    const float* b1 = (const float*)d_in[3];
    const float* W2 = (const float*)d_in[4];
    const float* b2 = (const float*)d_in[5];
    const float* Wl = (const float*)d_in[6];
    const float* bl = (const float*)d_in[7];
    float* out = (float*)d_out;

    const int* row = ei;        // edge_index[0]
    const int* col = ei + NE;   // edge_index[1]

    const int TB = 256;
    // CSR build (runs every replay; all int work, cheap)
    k_zero <<<(NN + TB - 1) / TB, TB>>>();
    k_hist <<<(NE + TB - 1) / TB, TB>>>(col);
    k_dinv <<<(NN + TB - 1) / TB, TB>>>();
    k_scan1<<<SCAN_NBLK, 1024>>>();
    k_scan2<<<1, 128>>>();
    k_scan3<<<SCAN_NBLK, 1024>>>();
    k_fill <<<(NE + TB - 1) / TB, TB>>>(row, col);

    // conv1: h0 = x@W1 ; h1 = relu(agg(h0)+b1)
    k_gemm<FIN, false><<<(NN + TB - 1) / TB, TB>>>(x, W1);
    k_agg<<<(NN * 32 + TB - 1) / TB, TB>>>(b1);

    // conv2: h0 = h1@W2 ; h1 = relu(agg(h0)+b2)
    k_gemm<HID, true><<<(NN + TB - 1) / TB, TB>>>(nullptr, W2);
    k_agg<<<(NN * 32 + TB - 1) / TB, TB>>>(b2);

    // edge head: per-node partials then per-edge sum
    k_head<<<(NN + TB - 1) / TB, TB>>>(Wl, bl);
    k_edge<<<(NE * 2 + TB - 1) / TB, TB>>>(row, col, out);
}